// round 1
// baseline (speedup 1.0000x reference)
#include <cuda_runtime.h>
#include <math.h>

// Problem constants
#define NFRAMES 16          // B*T = 4*4
#define IMG_H   480
#define IMG_W   640
#define NCH     20          // 4 + NSEM
#define PLANE   (IMG_H * IMG_W)   // 307200
#define DS_H    120         // 480/4
#define DS_W    160         // 640/4
#define NPIX    (DS_H * DS_W)     // 19200
#define VR      100
#define CELLS   (VR * VR)         // 10000
#define NSEM    16
#define NOUT    (2 + NSEM)        // 18
#define MIN_MAPPED 13
#define MAX_MAPPED 25       // exclusive

// Scratch accumulator: [frame][channel][y][x]; ch0=obstacle count ind., ch1=explored ind., ch2..17=sem sums
__device__ float g_acc[NFRAMES * NOUT * CELLS];

__global__ void zero_kernel() {
    int i = blockIdx.x * blockDim.x + threadIdx.x;
    int n = NFRAMES * NOUT * CELLS;
    if (i < n) g_acc[i] = 0.0f;
}

__global__ void scatter_kernel(const float* __restrict__ obs, float f_pix) {
    int idx = blockIdx.x * blockDim.x + threadIdx.x;
    if (idx >= NFRAMES * NPIX) return;
    int f   = idx / NPIX;
    int pix = idx - f * NPIX;
    int row = pix / DS_W;
    int col = pix - row * DS_W;

    const float* base = obs + (size_t)f * NCH * PLANE;
    int poff = (row * 4) * IMG_W + col * 4;   // strided ::4,::4 sampling

    float depth = base[3 * PLANE + poff];
    if (!(depth > 20.0f && depth < 500.0f)) return;

    float uu = (float)(col * 4);
    float vv = (float)(row * 4);

    // Match reference op order exactly: X = (uu-CX)*depth / F_PIX, etc.
    float X  = __fdiv_rn((uu - 320.0f) * depth, f_pix);
    float Zh = 88.0f + __fdiv_rn((240.0f - vv) * depth, f_pix);

    int xb = __float2int_rn(__fdiv_rn(X, 5.0f) + 50.0f);   // round half-even like jnp.round
    int yb = __float2int_rn(__fdiv_rn(depth, 5.0f));
    int zb = __float2int_rn(__fdiv_rn(Zh, 5.0f)) + 8;      // - MIN_VOX (= -8)

    if (xb < 0 || xb >= VR || yb < 0 || yb >= VR || zb < 0 || zb >= 80) return;

    int cell  = yb * VR + xb;
    float* acc = g_acc + (size_t)f * NOUT * CELLS;

    // explored: clip(count,0,1) is an indicator -> idempotent plain store (deterministic)
    acc[CELLS + cell] = 1.0f;
    // obstacle: indicator of any point with zb in [MIN_MAPPED, MAX_MAPPED)
    if (zb >= MIN_MAPPED && zb < MAX_MAPPED)
        acc[cell] = 1.0f;

    // semantic channels: real sums, need atomics
    #pragma unroll
    for (int c = 0; c < NSEM; c++) {
        float s = base[(4 + c) * PLANE + poff];
        atomicAdd(&acc[(2 + c) * CELLS + cell], s);
    }
}

__global__ void finalize_kernel(float* __restrict__ out) {
    int idx = blockIdx.x * blockDim.x + threadIdx.x;
    if (idx >= NFRAMES * CELLS) return;
    int f    = idx / CELLS;
    int cell = idx - f * CELLS;
    int y = cell / VR;
    int x = cell - y * VR;

    const float* acc = g_acc + (size_t)f * NOUT * CELLS;
    float* dst       = out   + (size_t)f * NOUT * CELLS;

    // obstacle: 3x3 max dilation ('SAME', init 0); acc[ch0] already in {0,1}
    float m = 0.0f;
    #pragma unroll
    for (int dy = -1; dy <= 1; dy++) {
        int yy = y + dy;
        if (yy < 0 || yy >= VR) continue;
        #pragma unroll
        for (int dx = -1; dx <= 1; dx++) {
            int xx = x + dx;
            if (xx < 0 || xx >= VR) continue;
            m = fmaxf(m, acc[yy * VR + xx]);
        }
    }
    dst[cell] = m;

    // explored (EXP_T = 1.0 -> identity divide), already indicator
    dst[CELLS + cell] = acc[CELLS + cell];

    // semantic: clip(sum / 5, 0, 1)
    #pragma unroll
    for (int c = 0; c < NSEM; c++) {
        float v = __fdiv_rn(acc[(2 + c) * CELLS + cell], 5.0f);
        dst[(2 + c) * CELLS + cell] = fminf(fmaxf(v, 0.0f), 1.0f);
    }
}

extern "C" void kernel_launch(void* const* d_in, const int* in_sizes, int n_in,
                              void* d_out, int out_size) {
    const float* obs = (const float*)d_in[0];   // seq_obs: (4,4,20,480,640) f32
    float* out = (float*)d_out;                 // (4,4,18,100,100) f32

    // F_PIX exactly as reference: W/2 / tan(deg2rad(HFOV/2)) computed in double,
    // then rounded to f32 (JAX weak-scalar promotion).
    float f_pix = (float)(320.0 / tan(39.5 * 3.14159265358979323846 / 180.0));

    int n_acc = NFRAMES * NOUT * CELLS;
    zero_kernel<<<(n_acc + 255) / 256, 256>>>();
    scatter_kernel<<<(NFRAMES * NPIX + 255) / 256, 256>>>(obs, f_pix);
    finalize_kernel<<<(NFRAMES * CELLS + 255) / 256, 256>>>(out);
}